// round 3
// baseline (speedup 1.0000x reference)
#include <cuda_runtime.h>
#include <cstdint>

#define D_MODEL 1024
#define L_SEQ   2048
#define BATCH   2
#define NST     16
#define RRANK   64
#define EPROJ   96
#define BLTOT   (BATCH * L_SEQ)   // 4096

// ---- scratch (static device globals; no allocation allowed) ----
__device__ float  g_dtlow[BLTOT * RRANK];            // [bl][r]           1 MiB
__device__ float  g_bc[BLTOT * 2 * NST];             // [bl][2n + {B,C}]  0.5 MiB
__device__ float2 g_deltax[BATCH * D_MODEL * L_SEQ]; // [b*D+d][t] = (delta, delta*x)  32 MiB

// =====================================================================
// Kernel 1: x_dbl = hidden @ W_xproj^T   (M=4096, E=96, K=1024)
// Writes dt_low (cols 0..63) compact, and B/C (cols 64..95) interleaved.
// grid 128 (BM=32), block 256
// =====================================================================
__global__ __launch_bounds__(256) void k_xproj(const float* __restrict__ X,
                                               const float* __restrict__ W)
{
    __shared__ float As[64][36];    // [k][m]  BM=32 (+4 pad)
    __shared__ float Ws[64][100];   // [k][e]  E=96 (+4 pad)

    const int tid = threadIdx.x;
    const int m0  = blockIdx.x * 32;
    const int tx  = tid & 15;       // e-group
    const int ty  = tid >> 4;       // m-group
    const int k4  = (tid & 15) * 4;
    const int rw  = tid >> 4;       // 0..15

    float acc[2][6];
#pragma unroll
    for (int i = 0; i < 2; i++)
#pragma unroll
        for (int j = 0; j < 6; j++) acc[i][j] = 0.f;

    for (int kk = 0; kk < D_MODEL; kk += 64) {
#pragma unroll
        for (int r = 0; r < 2; r++) {
            float4 v = *(const float4*)(X + (size_t)(m0 + rw + 16 * r) * D_MODEL + kk + k4);
            As[k4 + 0][rw + 16 * r] = v.x;
            As[k4 + 1][rw + 16 * r] = v.y;
            As[k4 + 2][rw + 16 * r] = v.z;
            As[k4 + 3][rw + 16 * r] = v.w;
        }
#pragma unroll
        for (int r = 0; r < 6; r++) {
            float4 v = *(const float4*)(W + (size_t)(rw + 16 * r) * D_MODEL + kk + k4);
            Ws[k4 + 0][rw + 16 * r] = v.x;
            Ws[k4 + 1][rw + 16 * r] = v.y;
            Ws[k4 + 2][rw + 16 * r] = v.z;
            Ws[k4 + 3][rw + 16 * r] = v.w;
        }
        __syncthreads();

#pragma unroll 16
        for (int k = 0; k < 64; k++) {
            float a0 = As[k][ty * 2 + 0];
            float a1 = As[k][ty * 2 + 1];
#pragma unroll
            for (int j = 0; j < 6; j++) {
                float b = Ws[k][tx + 16 * j];
                acc[0][j] = fmaf(a0, b, acc[0][j]);
                acc[1][j] = fmaf(a1, b, acc[1][j]);
            }
        }
        __syncthreads();
    }

#pragma unroll
    for (int i = 0; i < 2; i++) {
        int m = m0 + ty * 2 + i;
#pragma unroll
        for (int j = 0; j < 6; j++) {
            float v = acc[i][j];
            if (j < 4) {
                g_dtlow[(size_t)m * RRANK + tx + 16 * j] = v;      // dt_low cols 0..63
            } else if (j == 4) {
                g_bc[(size_t)m * 32 + 2 * tx + 0] = v;             // B, n = tx
            } else {
                g_bc[(size_t)m * 32 + 2 * tx + 1] = v;             // C, n = tx
            }
        }
    }
}

// =====================================================================
// Kernel 2: delta = softplus(dt_low @ W_dt^T + b_dt); write (delta, delta*x)
// transposed to [channel][t] layout via smem.  M=4096(bl) x N=1024(d), K=64.
// grid (16, 64), block 256
// =====================================================================
__device__ __forceinline__ float softplusf(float z)
{
    return fmaxf(z, 0.f) + log1pf(__expf(-fabsf(z)));
}

__global__ __launch_bounds__(256) void k_delta(const float* __restrict__ Wdt,
                                               const float* __restrict__ bdt,
                                               const float* __restrict__ X)
{
    __shared__ float smem[2 * 64 * 68];   // GEMM tiles, reused for transpose
    float (*As)[68] = (float (*)[68])smem;              // [k][bl]
    float (*Ws)[68] = (float (*)[68])(smem + 64 * 68);  // [k][d]

    const int tid = threadIdx.x;
    const int bl0 = blockIdx.y * 64;
    const int d0  = blockIdx.x * 64;
    const int k4  = (tid & 15) * 4;
    const int rw  = tid >> 4;

#pragma unroll
    for (int r = 0; r < 4; r++) {
        float4 a = *(const float4*)(g_dtlow + (size_t)(bl0 + rw + 16 * r) * RRANK + k4);
        As[k4 + 0][rw + 16 * r] = a.x;
        As[k4 + 1][rw + 16 * r] = a.y;
        As[k4 + 2][rw + 16 * r] = a.z;
        As[k4 + 3][rw + 16 * r] = a.w;
        float4 w = *(const float4*)(Wdt + (size_t)(d0 + rw + 16 * r) * RRANK + k4);
        Ws[k4 + 0][rw + 16 * r] = w.x;
        Ws[k4 + 1][rw + 16 * r] = w.y;
        Ws[k4 + 2][rw + 16 * r] = w.z;
        Ws[k4 + 3][rw + 16 * r] = w.w;
    }
    __syncthreads();

    const int tx = tid & 15;   // d-group
    const int ty = tid >> 4;   // bl-group
    float acc[4][4];
#pragma unroll
    for (int i = 0; i < 4; i++)
#pragma unroll
        for (int j = 0; j < 4; j++) acc[i][j] = 0.f;

#pragma unroll 16
    for (int k = 0; k < 64; k++) {
        float4 a = *(const float4*)&As[k][ty * 4];
        float4 w = *(const float4*)&Ws[k][tx * 4];
        acc[0][0] = fmaf(a.x, w.x, acc[0][0]); acc[0][1] = fmaf(a.x, w.y, acc[0][1]);
        acc[0][2] = fmaf(a.x, w.z, acc[0][2]); acc[0][3] = fmaf(a.x, w.w, acc[0][3]);
        acc[1][0] = fmaf(a.y, w.x, acc[1][0]); acc[1][1] = fmaf(a.y, w.y, acc[1][1]);
        acc[1][2] = fmaf(a.y, w.z, acc[1][2]); acc[1][3] = fmaf(a.y, w.w, acc[1][3]);
        acc[2][0] = fmaf(a.z, w.x, acc[2][0]); acc[2][1] = fmaf(a.z, w.y, acc[2][1]);
        acc[2][2] = fmaf(a.z, w.z, acc[2][2]); acc[2][3] = fmaf(a.z, w.w, acc[2][3]);
        acc[3][0] = fmaf(a.w, w.x, acc[3][0]); acc[3][1] = fmaf(a.w, w.y, acc[3][1]);
        acc[3][2] = fmaf(a.w, w.z, acc[3][2]); acc[3][3] = fmaf(a.w, w.w, acc[3][3]);
    }
    __syncthreads();   // tiles dead; reuse smem as float2 transpose buffer

    float2* st = (float2*)smem;       // st[d_local * 66 + t_local]
    float4 bv = *(const float4*)(bdt + d0 + tx * 4);
#pragma unroll
    for (int i = 0; i < 4; i++) {
        int bl = bl0 + ty * 4 + i;
        float4 xv = *(const float4*)(X + (size_t)bl * D_MODEL + d0 + tx * 4);
        float zs[4] = {acc[i][0] + bv.x, acc[i][1] + bv.y, acc[i][2] + bv.z, acc[i][3] + bv.w};
        float xs[4] = {xv.x, xv.y, xv.z, xv.w};
#pragma unroll
        for (int j = 0; j < 4; j++) {
            float dlt = softplusf(zs[j]);
            st[(size_t)(tx * 4 + j) * 66 + (ty * 4 + i)] = make_float2(dlt, dlt * xs[j]);
        }
    }
    __syncthreads();

    // coalesced copy-out: 64 d-rows x 64 t (each row = 32 float4 in gmem)
    const int b  = bl0 >> 11;            // bl0 / L_SEQ
    const int t0 = bl0 & (L_SEQ - 1);
    const int dl = tid >> 2;             // 0..63
    const int q  = tid & 3;              // 0..3
    const float4* srow = (const float4*)(st + (size_t)dl * 66);
    float4* dst = (float4*)(g_deltax + ((size_t)(b * D_MODEL + d0 + dl)) * L_SEQ + t0);
#pragma unroll
    for (int s = 0; s < 8; s++) dst[q * 8 + s] = srow[q * 8 + s];
}

// =====================================================================
// Kernel 3: selective scan. thread = (channel, n). 16 lanes per channel,
// 2 channels per warp, 16 channels per block. grid 128, block 256 (1 wave).
// =====================================================================
__device__ __forceinline__ float ex2f(float x)
{
    float r;
    asm("ex2.approx.ftz.f32 %0, %1;" : "=f"(r) : "f"(x));
    return r;
}

__global__ __launch_bounds__(256) void k_scan(const float* __restrict__ Alog,
                                              float* __restrict__ out)
{
    const int tid  = threadIdx.x;
    const int warp = tid >> 5;
    const int lane = tid & 31;
    const int half = lane >> 4;
    const int n    = lane & 15;
    const int c    = blockIdx.x * 16 + warp * 2 + half;   // channel = b*D + d
    const int b    = c >> 10;
    const int d    = c & (D_MODEL - 1);

    // A = -exp(A_log); pre-scale by log2(e) so dA = ex2(delta * A2)
    const float A2 = -__expf(Alog[d * NST + n]) * 1.4426950408889634f;

    const float4* __restrict__ dxp = (const float4*)(g_deltax + (size_t)c * L_SEQ); // 2 t per ld
    const float*  __restrict__ bcp = g_bc + ((size_t)b * L_SEQ) * 32 + 2 * n;
    float* __restrict__ yo = out + (size_t)b * L_SEQ * D_MODEL + d;

    float h = 0.f;
#pragma unroll 4
    for (int t2 = 0; t2 < L_SEQ / 2; t2++) {
        float4 dd  = dxp[t2];  // (delta_t, dx_t, delta_t1, dx_t1)
        float2 bc0 = *(const float2*)(bcp + (size_t)(2 * t2) * 32);
        float2 bc1 = *(const float2*)(bcp + (size_t)(2 * t2 + 1) * 32);

        float dA0 = ex2f(dd.x * A2);
        h = fmaf(dA0, h, dd.y * bc0.x);
        float y0 = h * bc0.y;
        y0 += __shfl_xor_sync(0xffffffffu, y0, 1);
        y0 += __shfl_xor_sync(0xffffffffu, y0, 2);
        y0 += __shfl_xor_sync(0xffffffffu, y0, 4);
        y0 += __shfl_xor_sync(0xffffffffu, y0, 8);

        float dA1 = ex2f(dd.z * A2);
        h = fmaf(dA1, h, dd.w * bc1.x);
        float y1 = h * bc1.y;
        y1 += __shfl_xor_sync(0xffffffffu, y1, 1);
        y1 += __shfl_xor_sync(0xffffffffu, y1, 2);
        y1 += __shfl_xor_sync(0xffffffffu, y1, 4);
        y1 += __shfl_xor_sync(0xffffffffu, y1, 8);

        if (n == 0) {
            yo[(size_t)(2 * t2) * D_MODEL]     = y0;
            yo[(size_t)(2 * t2 + 1) * D_MODEL] = y1;
        }
    }
}

// =====================================================================
extern "C" void kernel_launch(void* const* d_in, const int* in_sizes, int n_in,
                              void* d_out, int out_size)
{
    const float* X    = (const float*)d_in[0];   // hidden_states (B,L,D)
    const float* Wx   = (const float*)d_in[1];   // W_xproj (96,1024)
    const float* Wdt  = (const float*)d_in[2];   // W_dt (1024,64)
    const float* bdt  = (const float*)d_in[3];   // b_dt (1024)
    const float* Alog = (const float*)d_in[4];   // A_log (1024,16)
    float* out = (float*)d_out;

    k_xproj<<<128, 256>>>(X, Wx);
    k_delta<<<dim3(16, 64), 256>>>(Wdt, bdt, X);
    k_scan<<<128, 256>>>(Alog, out);
}

// round 4
// speedup vs baseline: 2.0412x; 2.0412x over previous
#include <cuda_runtime.h>
#include <cstdint>

#define D_MODEL 1024
#define L_SEQ   2048
#define BATCH   2
#define NST     16
#define RRANK   64
#define EPROJ   96
#define BLTOT   (BATCH * L_SEQ)   // 4096
#define GCH     16                // chunks per sequence
#define TCH     (L_SEQ / GCH)     // 128 timesteps per chunk
#define NCHAN   (BATCH * D_MODEL) // 2048

// ---- scratch (static device globals; no allocation allowed) ----
__device__ float  g_dtlow[BLTOT * RRANK];            // [bl][r]           1 MiB
__device__ float  g_bc[BLTOT * 2 * NST];             // [bl][2n + {B,C}]  0.5 MiB
__device__ float2 g_deltax[NCHAN * L_SEQ];           // [c][t] = (delta, delta*x)  32 MiB
__device__ float  g_cum[NCHAN * L_SEQ];              // [c][t] chunk-local cumsum(delta) 16 MiB
__device__ float  g_P [NCHAN * GCH * NST];           // chunk decay product   2 MiB
__device__ float  g_H [NCHAN * GCH * NST];           // chunk-local final h   2 MiB
__device__ float  g_hs[NCHAN * GCH * NST];           // h at chunk start      2 MiB

// =====================================================================
// Kernel 1: x_dbl = hidden @ W_xproj^T   (M=4096, E=96, K=1024)
// grid 128 (BM=32), block 256
// =====================================================================
__global__ __launch_bounds__(256) void k_xproj(const float* __restrict__ X,
                                               const float* __restrict__ W)
{
    __shared__ float As[64][36];    // [k][m]  BM=32 (+4 pad)
    __shared__ float Ws[64][100];   // [k][e]  E=96 (+4 pad)

    const int tid = threadIdx.x;
    const int m0  = blockIdx.x * 32;
    const int tx  = tid & 15;       // e-group
    const int ty  = tid >> 4;       // m-group
    const int k4  = (tid & 15) * 4;
    const int rw  = tid >> 4;       // 0..15

    float acc[2][6];
#pragma unroll
    for (int i = 0; i < 2; i++)
#pragma unroll
        for (int j = 0; j < 6; j++) acc[i][j] = 0.f;

    for (int kk = 0; kk < D_MODEL; kk += 64) {
#pragma unroll
        for (int r = 0; r < 2; r++) {
            float4 v = *(const float4*)(X + (size_t)(m0 + rw + 16 * r) * D_MODEL + kk + k4);
            As[k4 + 0][rw + 16 * r] = v.x;
            As[k4 + 1][rw + 16 * r] = v.y;
            As[k4 + 2][rw + 16 * r] = v.z;
            As[k4 + 3][rw + 16 * r] = v.w;
        }
#pragma unroll
        for (int r = 0; r < 6; r++) {
            float4 v = *(const float4*)(W + (size_t)(rw + 16 * r) * D_MODEL + kk + k4);
            Ws[k4 + 0][rw + 16 * r] = v.x;
            Ws[k4 + 1][rw + 16 * r] = v.y;
            Ws[k4 + 2][rw + 16 * r] = v.z;
            Ws[k4 + 3][rw + 16 * r] = v.w;
        }
        __syncthreads();

#pragma unroll 16
        for (int k = 0; k < 64; k++) {
            float a0 = As[k][ty * 2 + 0];
            float a1 = As[k][ty * 2 + 1];
#pragma unroll
            for (int j = 0; j < 6; j++) {
                float b = Ws[k][tx + 16 * j];
                acc[0][j] = fmaf(a0, b, acc[0][j]);
                acc[1][j] = fmaf(a1, b, acc[1][j]);
            }
        }
        __syncthreads();
    }

#pragma unroll
    for (int i = 0; i < 2; i++) {
        int m = m0 + ty * 2 + i;
#pragma unroll
        for (int j = 0; j < 6; j++) {
            float v = acc[i][j];
            if (j < 4) {
                g_dtlow[(size_t)m * RRANK + tx + 16 * j] = v;      // dt_low cols 0..63
            } else if (j == 4) {
                g_bc[(size_t)m * 32 + 2 * tx + 0] = v;             // B, n = tx
            } else {
                g_bc[(size_t)m * 32 + 2 * tx + 1] = v;             // C, n = tx
            }
        }
    }
}

// =====================================================================
// Kernel 2: delta = softplus(dt_low @ W_dt^T + b_dt); write (delta, delta*x)
// transposed to [channel][t] layout via smem.  grid (16, 64), block 256
// =====================================================================
__device__ __forceinline__ float softplusf(float z)
{
    return fmaxf(z, 0.f) + log1pf(__expf(-fabsf(z)));
}

__global__ __launch_bounds__(256) void k_delta(const float* __restrict__ Wdt,
                                               const float* __restrict__ bdt,
                                               const float* __restrict__ X)
{
    __shared__ float smem[2 * 64 * 68];   // GEMM tiles, reused for transpose
    float (*As)[68] = (float (*)[68])smem;              // [k][bl]
    float (*Ws)[68] = (float (*)[68])(smem + 64 * 68);  // [k][d]

    const int tid = threadIdx.x;
    const int bl0 = blockIdx.y * 64;
    const int d0  = blockIdx.x * 64;
    const int k4  = (tid & 15) * 4;
    const int rw  = tid >> 4;

#pragma unroll
    for (int r = 0; r < 4; r++) {
        float4 a = *(const float4*)(g_dtlow + (size_t)(bl0 + rw + 16 * r) * RRANK + k4);
        As[k4 + 0][rw + 16 * r] = a.x;
        As[k4 + 1][rw + 16 * r] = a.y;
        As[k4 + 2][rw + 16 * r] = a.z;
        As[k4 + 3][rw + 16 * r] = a.w;
        float4 w = *(const float4*)(Wdt + (size_t)(d0 + rw + 16 * r) * RRANK + k4);
        Ws[k4 + 0][rw + 16 * r] = w.x;
        Ws[k4 + 1][rw + 16 * r] = w.y;
        Ws[k4 + 2][rw + 16 * r] = w.z;
        Ws[k4 + 3][rw + 16 * r] = w.w;
    }
    __syncthreads();

    const int tx = tid & 15;   // d-group
    const int ty = tid >> 4;   // bl-group
    float acc[4][4];
#pragma unroll
    for (int i = 0; i < 4; i++)
#pragma unroll
        for (int j = 0; j < 4; j++) acc[i][j] = 0.f;

#pragma unroll 16
    for (int k = 0; k < 64; k++) {
        float4 a = *(const float4*)&As[k][ty * 4];
        float4 w = *(const float4*)&Ws[k][tx * 4];
        acc[0][0] = fmaf(a.x, w.x, acc[0][0]); acc[0][1] = fmaf(a.x, w.y, acc[0][1]);
        acc[0][2] = fmaf(a.x, w.z, acc[0][2]); acc[0][3] = fmaf(a.x, w.w, acc[0][3]);
        acc[1][0] = fmaf(a.y, w.x, acc[1][0]); acc[1][1] = fmaf(a.y, w.y, acc[1][1]);
        acc[1][2] = fmaf(a.y, w.z, acc[1][2]); acc[1][3] = fmaf(a.y, w.w, acc[1][3]);
        acc[2][0] = fmaf(a.z, w.x, acc[2][0]); acc[2][1] = fmaf(a.z, w.y, acc[2][1]);
        acc[2][2] = fmaf(a.z, w.z, acc[2][2]); acc[2][3] = fmaf(a.z, w.w, acc[2][3]);
        acc[3][0] = fmaf(a.w, w.x, acc[3][0]); acc[3][1] = fmaf(a.w, w.y, acc[3][1]);
        acc[3][2] = fmaf(a.w, w.z, acc[3][2]); acc[3][3] = fmaf(a.w, w.w, acc[3][3]);
    }
    __syncthreads();   // tiles dead; reuse smem as float2 transpose buffer

    float2* st = (float2*)smem;       // st[d_local * 66 + t_local]
    float4 bv = *(const float4*)(bdt + d0 + tx * 4);
#pragma unroll
    for (int i = 0; i < 4; i++) {
        int bl = bl0 + ty * 4 + i;
        float4 xv = *(const float4*)(X + (size_t)bl * D_MODEL + d0 + tx * 4);
        float zs[4] = {acc[i][0] + bv.x, acc[i][1] + bv.y, acc[i][2] + bv.z, acc[i][3] + bv.w};
        float xs[4] = {xv.x, xv.y, xv.z, xv.w};
#pragma unroll
        for (int j = 0; j < 4; j++) {
            float dlt = softplusf(zs[j]);
            st[(size_t)(tx * 4 + j) * 66 + (ty * 4 + i)] = make_float2(dlt, dlt * xs[j]);
        }
    }
    __syncthreads();

    // coalesced copy-out: 64 d-rows x 64 t (each row = 32 float4 in gmem)
    const int b  = bl0 >> 11;            // bl0 / L_SEQ
    const int t0 = bl0 & (L_SEQ - 1);
    const int dl = tid >> 2;             // 0..63
    const int q  = tid & 3;              // 0..3
    const float4* srow = (const float4*)(st + (size_t)dl * 66);
    float4* dst = (float4*)(g_deltax + ((size_t)(b * D_MODEL + d0 + dl)) * L_SEQ + t0);
#pragma unroll
    for (int s = 0; s < 8; s++) dst[q * 8 + s] = srow[q * 8 + s];
}

// =====================================================================
// Chunked selective scan.
// Warp layout (pass1/pass3): global warp W -> chunk g = W & 15,
// channel c = (W>>4)*2 + half  (half = lane>>4, n = lane&15).
// g is warp-uniform; each half-warp owns one (channel, chunk).
// =====================================================================
__device__ __forceinline__ float ex2f(float x)
{
    float r;
    asm("ex2.approx.ftz.f32 %0, %1;" : "=f"(r) : "f"(x));
    return r;
}

__device__ __forceinline__ float redux16(float y)
{
    y += __shfl_xor_sync(0xffffffffu, y, 1);
    y += __shfl_xor_sync(0xffffffffu, y, 2);
    y += __shfl_xor_sync(0xffffffffu, y, 4);
    y += __shfl_xor_sync(0xffffffffu, y, 8);
    return y;
}

// ---- pass 1: local scan per chunk (h starts at 0), record cumsum(delta),
//              per-chunk decay product P and local final state H.
// grid 2048, block 256
__global__ __launch_bounds__(256) void k_scan1(const float* __restrict__ Alog,
                                               float* __restrict__ out)
{
    const int tid  = threadIdx.x;
    const int lane = tid & 31;
    const int half = lane >> 4;
    const int n    = lane & 15;
    const int W    = blockIdx.x * 8 + (tid >> 5);
    const int g    = W & (GCH - 1);
    const int c    = ((W >> 4) << 1) + half;
    const int b    = c >> 10;
    const int d    = c & (D_MODEL - 1);
    const int t0   = g * TCH;

    const float A2 = -__expf(Alog[d * NST + n]) * 1.4426950408889634f;

    const float4* __restrict__ dxp = (const float4*)(g_deltax + (size_t)c * L_SEQ) + (t0 >> 1);
    const float*  __restrict__ bcp = g_bc + ((size_t)b * L_SEQ + t0) * 32 + 2 * n;
    float* __restrict__ yo   = out + ((size_t)b * L_SEQ + t0) * D_MODEL + d;
    float* __restrict__ cump = g_cum + (size_t)c * L_SEQ + t0;

    float h = 0.f, cum = 0.f;
#pragma unroll 4
    for (int i = 0; i < TCH / 2; i++) {
        float4 dd  = dxp[i];  // (delta_t, dx_t, delta_t1, dx_t1)
        float2 bc0 = *(const float2*)(bcp + (size_t)(2 * i) * 32);
        float2 bc1 = *(const float2*)(bcp + (size_t)(2 * i + 1) * 32);

        float dA0 = ex2f(dd.x * A2);
        h = fmaf(dA0, h, dd.y * bc0.x);
        float y0 = redux16(h * bc0.y);
        cum += dd.x;
        float c0 = cum;

        float dA1 = ex2f(dd.z * A2);
        h = fmaf(dA1, h, dd.w * bc1.x);
        float y1 = redux16(h * bc1.y);
        cum += dd.z;

        if (n == 0) {
            yo[(size_t)(2 * i) * D_MODEL]     = y0;
            yo[(size_t)(2 * i + 1) * D_MODEL] = y1;
            *(float2*)(cump + 2 * i) = make_float2(c0, cum);
        }
    }

    const size_t o = ((size_t)c * GCH + g) * NST + n;
    g_P[o] = ex2f(cum * A2);
    g_H[o] = h;
}

// ---- pass 2: sequential prefix over chunks (tiny). grid 128, block 256
__global__ __launch_bounds__(256) void k_fix()
{
    const int idx = blockIdx.x * 256 + threadIdx.x;   // 0..32767
    const int c = idx >> 4;
    const int n = idx & 15;
    float hs = 0.f;
#pragma unroll
    for (int g = 0; g < GCH; g++) {
        const size_t o = ((size_t)c * GCH + g) * NST + n;
        g_hs[o] = hs;
        hs = g_H[o] + g_P[o] * hs;
    }
}

// ---- pass 3: cross-chunk correction  y_t += sum_n C_tn * ex2(A2*cum_t) * hs_n
// grid 2048, block 256
__global__ __launch_bounds__(256) void k_scan3(const float* __restrict__ Alog,
                                               float* __restrict__ out)
{
    const int tid  = threadIdx.x;
    const int lane = tid & 31;
    const int half = lane >> 4;
    const int n    = lane & 15;
    const int W    = blockIdx.x * 8 + (tid >> 5);
    const int g    = W & (GCH - 1);
    if (g == 0) return;                 // warp-uniform: first chunk needs no fix
    const int c    = ((W >> 4) << 1) + half;
    const int b    = c >> 10;
    const int d    = c & (D_MODEL - 1);
    const int t0   = g * TCH;

    const float A2 = -__expf(Alog[d * NST + n]) * 1.4426950408889634f;
    const float hs = g_hs[((size_t)c * GCH + g) * NST + n];

    const float* __restrict__ cump = g_cum + (size_t)c * L_SEQ + t0;
    const float* __restrict__ cp   = g_bc + ((size_t)b * L_SEQ + t0) * 32 + 2 * n + 1;
    float* __restrict__ yo = out + ((size_t)b * L_SEQ + t0) * D_MODEL + d;

#pragma unroll 4
    for (int i = 0; i < TCH / 2; i++) {
        float2 cc = *(const float2*)(cump + 2 * i);
        float C0 = cp[(size_t)(2 * i) * 32];
        float C1 = cp[(size_t)(2 * i + 1) * 32];
        float y0 = redux16(ex2f(cc.x * A2) * hs * C0);
        float y1 = redux16(ex2f(cc.y * A2) * hs * C1);
        if (n == 0) {
            yo[(size_t)(2 * i) * D_MODEL]     += y0;
            yo[(size_t)(2 * i + 1) * D_MODEL] += y1;
        }
    }
}

// =====================================================================
extern "C" void kernel_launch(void* const* d_in, const int* in_sizes, int n_in,
                              void* d_out, int out_size)
{
    const float* X    = (const float*)d_in[0];   // hidden_states (B,L,D)
    const float* Wx   = (const float*)d_in[1];   // W_xproj (96,1024)
    const float* Wdt  = (const float*)d_in[2];   // W_dt (1024,64)
    const float* bdt  = (const float*)d_in[3];   // b_dt (1024)
    const float* Alog = (const float*)d_in[4];   // A_log (1024,16)
    float* out = (float*)d_out;

    k_xproj<<<128, 256>>>(X, Wx);
    k_delta<<<dim3(16, 64), 256>>>(Wdt, bdt, X);
    k_scan1<<<2048, 256>>>(Alog, out);
    k_fix<<<128, 256>>>();
    k_scan3<<<2048, 256>>>(Alog, out);
}

// round 6
// speedup vs baseline: 2.6217x; 1.2844x over previous
#include <cuda_runtime.h>
#include <cstdint>

#define D_MODEL 1024
#define L_SEQ   2048
#define BATCH   2
#define NST     16
#define RRANK   64
#define EPROJ   96
#define BLTOT   (BATCH * L_SEQ)   // 4096
#define GCH     16                // chunks per sequence
#define TCH     (L_SEQ / GCH)     // 128 timesteps per chunk
#define NCHAN   (BATCH * D_MODEL) // 2048

// ---- scratch (static device globals; no allocation allowed) ----
__device__ float  g_dtlow[BLTOT * RRANK];            // [bl][r]
__device__ float  g_bc[BLTOT * 2 * NST];             // [bl][2n + {B,C}]
__device__ float2 g_deltax[NCHAN * L_SEQ];           // [c][t] = (delta, delta*x)
__device__ float  g_cum[NCHAN * L_SEQ];              // [c][t] chunk-local cumsum(delta)
__device__ float  g_P [NCHAN * GCH * NST];           // chunk decay product
__device__ float  g_H [NCHAN * GCH * NST];           // chunk-local final h
__device__ float  g_hs[NCHAN * GCH * NST];           // h at chunk start

// =====================================================================
// Kernel 0: zero the atomic accumulation buffers (g_dtlow, g_bc)
// grid 384, block 256, one float4 per thread
// =====================================================================
__global__ __launch_bounds__(256) void k_zero()
{
    const int i = blockIdx.x * 256 + threadIdx.x;
    if (blockIdx.x < 256) {
        ((float4*)g_dtlow)[i] = make_float4(0.f, 0.f, 0.f, 0.f);
    } else {
        ((float4*)g_bc)[i - 65536] = make_float4(0.f, 0.f, 0.f, 0.f);
    }
}

// =====================================================================
// Kernel 1: x_dbl = hidden @ W_xproj^T   (M=4096, E=96, K=1024)
// BM=32, K-split x2 (512 each), thread tile 4m x 6e, 128 threads.
// grid (128, 2), block 128.  Accumulate with atomicAdd (zeroed by k_zero).
// =====================================================================
__global__ __launch_bounds__(128) void k_xproj(const float* __restrict__ X,
                                               const float* __restrict__ W)
{
    __shared__ float As[64][36];    // [k][m]  BM=32 (+4 pad)
    __shared__ float Ws[64][100];   // [k][e]  E=96 (+4 pad)

    const int tid = threadIdx.x;            // 0..127
    const int m0  = blockIdx.x * 32;
    const int kk0 = blockIdx.y * 512;
    const int tx  = tid & 15;               // e-group: e = tx + 16j
    const int ty  = tid >> 4;               // m-group: m = ty*4 + i  (0..7)
    const int k4  = (tid & 15) * 4;
    const int rw  = tid >> 4;               // 0..7

    float acc[4][6];
#pragma unroll
    for (int i = 0; i < 4; i++)
#pragma unroll
        for (int j = 0; j < 6; j++) acc[i][j] = 0.f;

    for (int kk = kk0; kk < kk0 + 512; kk += 64) {
#pragma unroll
        for (int s = 0; s < 4; s++) {       // 32 m-rows
            int row = rw + 8 * s;
            float4 v = *(const float4*)(X + (size_t)(m0 + row) * D_MODEL + kk + k4);
            As[k4 + 0][row] = v.x;
            As[k4 + 1][row] = v.y;
            As[k4 + 2][row] = v.z;
            As[k4 + 3][row] = v.w;
        }
#pragma unroll
        for (int s = 0; s < 12; s++) {      // 96 e-rows
            int row = rw + 8 * s;
            float4 v = *(const float4*)(W + (size_t)row * D_MODEL + kk + k4);
            Ws[k4 + 0][row] = v.x;
            Ws[k4 + 1][row] = v.y;
            Ws[k4 + 2][row] = v.z;
            Ws[k4 + 3][row] = v.w;
        }
        __syncthreads();

#pragma unroll 8
        for (int k = 0; k < 64; k++) {
            float4 a = *(const float4*)&As[k][ty * 4];
#pragma unroll
            for (int j = 0; j < 6; j++) {
                float b = Ws[k][tx + 16 * j];
                acc[0][j] = fmaf(a.x, b, acc[0][j]);
                acc[1][j] = fmaf(a.y, b, acc[1][j]);
                acc[2][j] = fmaf(a.z, b, acc[2][j]);
                acc[3][j] = fmaf(a.w, b, acc[3][j]);
            }
        }
        __syncthreads();
    }

#pragma unroll
    for (int i = 0; i < 4; i++) {
        int m = m0 + ty * 4 + i;
#pragma unroll
        for (int j = 0; j < 6; j++) {
            int e = tx + 16 * j;
            float v = acc[i][j];
            if (e < 64) {
                atomicAdd(&g_dtlow[(size_t)m * RRANK + e], v);
            } else if (e < 80) {
                atomicAdd(&g_bc[(size_t)m * 32 + 2 * (e - 64) + 0], v);   // B
            } else {
                atomicAdd(&g_bc[(size_t)m * 32 + 2 * (e - 80) + 1], v);   // C
            }
        }
    }
}

// =====================================================================
// Kernel 2: delta = softplus(dt_low @ W_dt^T + b_dt); write (delta, delta*x)
// transposed to [channel][t] layout via smem.  grid (16, 64), block 256
// =====================================================================
__device__ __forceinline__ float softplusf(float z)
{
    return fmaxf(z, 0.f) + log1pf(__expf(-fabsf(z)));
}

__global__ __launch_bounds__(256) void k_delta(const float* __restrict__ Wdt,
                                               const float* __restrict__ bdt,
                                               const float* __restrict__ X)
{
    __shared__ float smem[2 * 64 * 68];   // GEMM tiles, reused for transpose
    float (*As)[68] = (float (*)[68])smem;              // [k][bl]
    float (*Ws)[68] = (float (*)[68])(smem + 64 * 68);  // [k][d]

    const int tid = threadIdx.x;
    const int bl0 = blockIdx.y * 64;
    const int d0  = blockIdx.x * 64;
    const int k4  = (tid & 15) * 4;
    const int rw  = tid >> 4;

#pragma unroll
    for (int r = 0; r < 4; r++) {
        float4 a = *(const float4*)(g_dtlow + (size_t)(bl0 + rw + 16 * r) * RRANK + k4);
        As[k4 + 0][rw + 16 * r] = a.x;
        As[k4 + 1][rw + 16 * r] = a.y;
        As[k4 + 2][rw + 16 * r] = a.z;
        As[k4 + 3][rw + 16 * r] = a.w;
        float4 w = *(const float4*)(Wdt + (size_t)(d0 + rw + 16 * r) * RRANK + k4);
        Ws[k4 + 0][rw + 16 * r] = w.x;
        Ws[k4 + 1][rw + 16 * r] = w.y;
        Ws[k4 + 2][rw + 16 * r] = w.z;
        Ws[k4 + 3][rw + 16 * r] = w.w;
    }
    __syncthreads();

    const int tx = tid & 15;   // d-group
    const int ty = tid >> 4;   // bl-group
    float acc[4][4];
#pragma unroll
    for (int i = 0; i < 4; i++)
#pragma unroll
        for (int j = 0; j < 4; j++) acc[i][j] = 0.f;

#pragma unroll 16
    for (int k = 0; k < 64; k++) {
        float4 a = *(const float4*)&As[k][ty * 4];
        float4 w = *(const float4*)&Ws[k][tx * 4];
        acc[0][0] = fmaf(a.x, w.x, acc[0][0]); acc[0][1] = fmaf(a.x, w.y, acc[0][1]);
        acc[0][2] = fmaf(a.x, w.z, acc[0][2]); acc[0][3] = fmaf(a.x, w.w, acc[0][3]);
        acc[1][0] = fmaf(a.y, w.x, acc[1][0]); acc[1][1] = fmaf(a.y, w.y, acc[1][1]);
        acc[1][2] = fmaf(a.y, w.z, acc[1][2]); acc[1][3] = fmaf(a.y, w.w, acc[1][3]);
        acc[2][0] = fmaf(a.z, w.x, acc[2][0]); acc[2][1] = fmaf(a.z, w.y, acc[2][1]);
        acc[2][2] = fmaf(a.z, w.z, acc[2][2]); acc[2][3] = fmaf(a.z, w.w, acc[2][3]);
        acc[3][0] = fmaf(a.w, w.x, acc[3][0]); acc[3][1] = fmaf(a.w, w.y, acc[3][1]);
        acc[3][2] = fmaf(a.w, w.z, acc[3][2]); acc[3][3] = fmaf(a.w, w.w, acc[3][3]);
    }
    __syncthreads();   // tiles dead; reuse smem as float2 transpose buffer

    float2* st = (float2*)smem;       // st[d_local * 66 + t_local]
    float4 bv = *(const float4*)(bdt + d0 + tx * 4);
#pragma unroll
    for (int i = 0; i < 4; i++) {
        int bl = bl0 + ty * 4 + i;
        float4 xv = *(const float4*)(X + (size_t)bl * D_MODEL + d0 + tx * 4);
        float zs[4] = {acc[i][0] + bv.x, acc[i][1] + bv.y, acc[i][2] + bv.z, acc[i][3] + bv.w};
        float xs[4] = {xv.x, xv.y, xv.z, xv.w};
#pragma unroll
        for (int j = 0; j < 4; j++) {
            float dlt = softplusf(zs[j]);
            st[(size_t)(tx * 4 + j) * 66 + (ty * 4 + i)] = make_float2(dlt, dlt * xs[j]);
        }
    }
    __syncthreads();

    // coalesced copy-out: 64 d-rows x 64 t (each row = 32 float4 in gmem)
    const int b  = bl0 >> 11;            // bl0 / L_SEQ
    const int t0 = bl0 & (L_SEQ - 1);
    const int dl = tid >> 2;             // 0..63
    const int q  = tid & 3;              // 0..3
    const float4* srow = (const float4*)(st + (size_t)dl * 66);
    float4* dst = (float4*)(g_deltax + ((size_t)(b * D_MODEL + d0 + dl)) * L_SEQ + t0);
#pragma unroll
    for (int s = 0; s < 8; s++) dst[q * 8 + s] = srow[q * 8 + s];
}

// =====================================================================
// Chunked selective scan.  Block = 16 consecutive channels x 1 chunk:
//   g  = blockIdx.x & 15, c0 = (blockIdx.x >> 4) * 16
//   warp w (0..7), half = lane>>4, ch = 2w + half, c = c0 + ch, n = lane&15
// y and cum staged in smem, written coalesced at the end.
// =====================================================================
__device__ __forceinline__ float ex2f(float x)
{
    float r;
    asm("ex2.approx.ftz.f32 %0, %1;" : "=f"(r) : "f"(x));
    return r;
}

__device__ __forceinline__ float redux16(float y)
{
    y += __shfl_xor_sync(0xffffffffu, y, 1);
    y += __shfl_xor_sync(0xffffffffu, y, 2);
    y += __shfl_xor_sync(0xffffffffu, y, 4);
    y += __shfl_xor_sync(0xffffffffu, y, 8);
    return y;
}

// ---- pass 1: local scan per chunk (h starts at 0). grid 2048, block 256
__global__ __launch_bounds__(256) void k_scan1(const float* __restrict__ Alog,
                                               float* __restrict__ out)
{
    __shared__ float ybuf[TCH][16];       // [t][ch]
    __shared__ float cumbuf[16][TCH];     // [ch][t]

    const int tid  = threadIdx.x;
    const int lane = tid & 31;
    const int half = lane >> 4;
    const int n    = lane & 15;
    const int g    = blockIdx.x & (GCH - 1);
    const int c0   = (blockIdx.x >> 4) << 4;
    const int ch   = ((tid >> 5) << 1) + half;
    const int c    = c0 + ch;
    const int b    = c >> 10;
    const int d    = c & (D_MODEL - 1);
    const int t0   = g * TCH;

    const float A2 = -__expf(Alog[d * NST + n]) * 1.4426950408889634f;

    const float4* __restrict__ dxp = (const float4*)(g_deltax + (size_t)c * L_SEQ) + (t0 >> 1);
    const float*  __restrict__ bcp = g_bc + ((size_t)b * L_SEQ + t0) * 32 + 2 * n;

    float h = 0.f, cum = 0.f;
#pragma unroll 4
    for (int i = 0; i < TCH / 2; i++) {
        float4 dd  = dxp[i];  // (delta_t, dx_t, delta_t1, dx_t1)
        float2 bc0 = *(const float2*)(bcp + (size_t)(2 * i) * 32);
        float2 bc1 = *(const float2*)(bcp + (size_t)(2 * i + 1) * 32);

        float dA0 = ex2f(dd.x * A2);
        h = fmaf(dA0, h, dd.y * bc0.x);
        float y0 = redux16(h * bc0.y);
        cum += dd.x;
        float cv0 = cum;

        float dA1 = ex2f(dd.z * A2);
        h = fmaf(dA1, h, dd.w * bc1.x);
        float y1 = redux16(h * bc1.y);
        cum += dd.z;

        if (n == 0) {
            ybuf[2 * i + 0][ch] = y0;
            ybuf[2 * i + 1][ch] = y1;
            cumbuf[ch][2 * i + 0] = cv0;
            cumbuf[ch][2 * i + 1] = cum;
        }
    }

    const size_t o = ((size_t)c * GCH + g) * NST + n;
    g_P[o] = ex2f(cum * A2);
    g_H[o] = h;
    __syncthreads();

    // coalesced copy-out of y: 128 t-rows x 16 d (64B each)
    const int d0 = c0 & (D_MODEL - 1);
    float* __restrict__ yo = out + ((size_t)b * L_SEQ + t0) * D_MODEL + d0;
#pragma unroll
    for (int s = 0; s < 2; s++) {
        int fid = tid * 2 + s;           // 0..511
        int t = fid >> 2, q = fid & 3;
        *(float4*)(yo + (size_t)t * D_MODEL + q * 4) = *(const float4*)&ybuf[t][q * 4];
    }
    // coalesced copy-out of cum: 16 c-rows x 128 t
#pragma unroll
    for (int s = 0; s < 2; s++) {
        int fid = tid * 2 + s;           // 0..511
        int cr = fid >> 5, tq = fid & 31;
        *(float4*)(g_cum + (size_t)(c0 + cr) * L_SEQ + t0 + tq * 4) =
            *(const float4*)&cumbuf[cr][tq * 4];
    }
}

// ---- pass 2: prefix over chunks, loads hoisted for MLP. grid 128, block 256
__global__ __launch_bounds__(256) void k_fix()
{
    const int idx = blockIdx.x * 256 + threadIdx.x;   // 0..32767
    const int c = idx >> 4;
    const int n = idx & 15;
    const size_t base = (size_t)c * GCH * NST + n;

    float P[GCH], H[GCH];
#pragma unroll
    for (int g = 0; g < GCH; g++) {
        P[g] = g_P[base + (size_t)g * NST];
        H[g] = g_H[base + (size_t)g * NST];
    }
    float hs = 0.f;
#pragma unroll
    for (int g = 0; g < GCH; g++) {
        g_hs[base + (size_t)g * NST] = hs;
        hs = fmaf(P[g], hs, H[g]);
    }
}

// ---- pass 3: cross-chunk correction, coalesced RMW on out. grid 2048
__global__ __launch_bounds__(256) void k_scan3(const float* __restrict__ Alog,
                                               float* __restrict__ out)
{
    __shared__ float ybuf[TCH][16];

    const int g = blockIdx.x & (GCH - 1);
    if (g == 0) return;                  // first chunk needs no correction

    const int tid  = threadIdx.x;
    const int lane = tid & 31;
    const int half = lane >> 4;
    const int n    = lane & 15;
    const int c0   = (blockIdx.x >> 4) << 4;
    const int ch   = ((tid >> 5) << 1) + half;
    const int c    = c0 + ch;
    const int b    = c >> 10;
    const int d    = c & (D_MODEL - 1);
    const int t0   = g * TCH;

    const float A2 = -__expf(Alog[d * NST + n]) * 1.4426950408889634f;
    const float hs = g_hs[((size_t)c * GCH + g) * NST + n];

    const float* __restrict__ cump = g_cum + (size_t)c * L_SEQ + t0;
    const float* __restrict__ cp   = g_bc + ((size_t)b * L_SEQ + t0) * 32 + 2 * n + 1;

#pragma unroll 4
    for (int i = 0; i < TCH / 2; i++) {
        float2 cc = *(const float2*)(cump + 2 * i);
        float C0 = cp[(size_t)(2 * i) * 32];
        float C1 = cp[(size_t)(2 * i + 1) * 32];
        float y0 = redux16(ex2f(cc.x * A2) * hs * C0);
        float y1 = redux16(ex2f(cc.y * A2) * hs * C1);
        if (n == 0) {
            ybuf[2 * i + 0][ch] = y0;
            ybuf[2 * i + 1][ch] = y1;
        }
    }
    __syncthreads();

    const int d0 = c0 & (D_MODEL - 1);
    float* __restrict__ yo = out + ((size_t)b * L_SEQ + t0) * D_MODEL + d0;
#pragma unroll
    for (int s = 0; s < 2; s++) {
        int fid = tid * 2 + s;           // 0..511
        int t = fid >> 2, q = fid & 3;
        float4* p = (float4*)(yo + (size_t)t * D_MODEL + q * 4);
        float4 v = *p;
        const float4 a = *(const float4*)&ybuf[t][q * 4];
        v.x += a.x; v.y += a.y; v.z += a.z; v.w += a.w;
        *p = v;
    }
}

// =====================================================================
extern "C" void kernel_launch(void* const* d_in, const int* in_sizes, int n_in,
                              void* d_out, int out_size)
{
    const float* X    = (const float*)d_in[0];   // hidden_states (B,L,D)
    const float* Wx   = (const float*)d_in[1];   // W_xproj (96,1024)
    const float* Wdt  = (const float*)d_in[2];   // W_dt (1024,64)
    const float* bdt  = (const float*)d_in[3];   // b_dt (1024)
    const float* Alog = (const float*)d_in[4];   // A_log (1024,16)
    float* out = (float*)d_out;

    k_zero <<<384, 256>>>();
    k_xproj<<<dim3(128, 2), 128>>>(X, Wx);
    k_delta<<<dim3(16, 64), 256>>>(Wdt, bdt, X);
    k_scan1<<<2048, 256>>>(Alog, out);
    k_fix  <<<128, 256>>>();
    k_scan3<<<2048, 256>>>(Alog, out);
}

// round 8
// speedup vs baseline: 4.4272x; 1.6886x over previous
#include <cuda_runtime.h>
#include <cstdint>

#define D_MODEL 1024
#define L_SEQ   2048
#define BATCH   2
#define NST     16
#define RRANK   64
#define EPROJ   96
#define BLTOT   (BATCH * L_SEQ)   // 4096
#define GCH     16                // chunks per sequence
#define TCH     (L_SEQ / GCH)     // 128 timesteps per chunk
#define NCHAN   (BATCH * D_MODEL) // 2048

// ---- scratch (static device globals; no allocation allowed) ----
__device__ float  g_dtlow[BLTOT * RRANK];            // [bl][r]
__device__ float  g_bc[BLTOT * 2 * NST];             // [bl][2n + {B,C}]
__device__ float2 g_deltax[NCHAN * L_SEQ];           // [c][t] = (delta, delta*x)
__device__ float  g_P [NCHAN * GCH * NST];           // chunk decay product
__device__ float  g_H [NCHAN * GCH * NST];           // chunk-local final h
__device__ float  g_hs[NCHAN * GCH * NST];           // h at chunk start

// =====================================================================
// Kernel 0: zero the atomic accumulation buffers (g_dtlow, g_bc)
// =====================================================================
__global__ __launch_bounds__(256) void k_zero()
{
    const int i = blockIdx.x * 256 + threadIdx.x;
    if (blockIdx.x < 256) {
        ((float4*)g_dtlow)[i] = make_float4(0.f, 0.f, 0.f, 0.f);
    } else {
        ((float4*)g_bc)[i - 65536] = make_float4(0.f, 0.f, 0.f, 0.f);
    }
}

// =====================================================================
// Kernel 1: x_dbl = hidden @ W_xproj^T   (M=4096, E=96, K=1024)
// BM=32, K-split x2, thread tile 4m x 6e, grid (128,2), block 128.
// =====================================================================
__global__ __launch_bounds__(128) void k_xproj(const float* __restrict__ X,
                                               const float* __restrict__ W)
{
    __shared__ float As[64][36];    // [k][m]
    __shared__ float Ws[64][100];   // [k][e]

    const int tid = threadIdx.x;
    const int m0  = blockIdx.x * 32;
    const int kk0 = blockIdx.y * 512;
    const int tx  = tid & 15;
    const int ty  = tid >> 4;
    const int k4  = (tid & 15) * 4;
    const int rw  = tid >> 4;

    float acc[4][6];
#pragma unroll
    for (int i = 0; i < 4; i++)
#pragma unroll
        for (int j = 0; j < 6; j++) acc[i][j] = 0.f;

    for (int kk = kk0; kk < kk0 + 512; kk += 64) {
#pragma unroll
        for (int s = 0; s < 4; s++) {
            int row = rw + 8 * s;
            float4 v = *(const float4*)(X + (size_t)(m0 + row) * D_MODEL + kk + k4);
            As[k4 + 0][row] = v.x;
            As[k4 + 1][row] = v.y;
            As[k4 + 2][row] = v.z;
            As[k4 + 3][row] = v.w;
        }
#pragma unroll
        for (int s = 0; s < 12; s++) {
            int row = rw + 8 * s;
            float4 v = *(const float4*)(W + (size_t)row * D_MODEL + kk + k4);
            Ws[k4 + 0][row] = v.x;
            Ws[k4 + 1][row] = v.y;
            Ws[k4 + 2][row] = v.z;
            Ws[k4 + 3][row] = v.w;
        }
        __syncthreads();

#pragma unroll 8
        for (int k = 0; k < 64; k++) {
            float4 a = *(const float4*)&As[k][ty * 4];
#pragma unroll
            for (int j = 0; j < 6; j++) {
                float b = Ws[k][tx + 16 * j];
                acc[0][j] = fmaf(a.x, b, acc[0][j]);
                acc[1][j] = fmaf(a.y, b, acc[1][j]);
                acc[2][j] = fmaf(a.z, b, acc[2][j]);
                acc[3][j] = fmaf(a.w, b, acc[3][j]);
            }
        }
        __syncthreads();
    }

#pragma unroll
    for (int i = 0; i < 4; i++) {
        int m = m0 + ty * 4 + i;
#pragma unroll
        for (int j = 0; j < 6; j++) {
            int e = tx + 16 * j;
            float v = acc[i][j];
            if (e < 64) {
                atomicAdd(&g_dtlow[(size_t)m * RRANK + e], v);
            } else if (e < 80) {
                atomicAdd(&g_bc[(size_t)m * 32 + 2 * (e - 64) + 0], v);   // B
            } else {
                atomicAdd(&g_bc[(size_t)m * 32 + 2 * (e - 80) + 1], v);   // C
            }
        }
    }
}

// =====================================================================
// Kernel 2: delta = softplus(dt_low @ W_dt^T + b_dt); write (delta, delta*x)
// transposed to [channel][t] layout via smem.  grid (16, 64), block 256
// =====================================================================
__device__ __forceinline__ float softplusf(float z)
{
    return fmaxf(z, 0.f) + log1pf(__expf(-fabsf(z)));
}

__global__ __launch_bounds__(256) void k_delta(const float* __restrict__ Wdt,
                                               const float* __restrict__ bdt,
                                               const float* __restrict__ X)
{
    __shared__ float smem[2 * 64 * 68];
    float (*As)[68] = (float (*)[68])smem;              // [k][bl]
    float (*Ws)[68] = (float (*)[68])(smem + 64 * 68);  // [k][d]

    const int tid = threadIdx.x;
    const int bl0 = blockIdx.y * 64;
    const int d0  = blockIdx.x * 64;
    const int k4  = (tid & 15) * 4;
    const int rw  = tid >> 4;

#pragma unroll
    for (int r = 0; r < 4; r++) {
        float4 a = *(const float4*)(g_dtlow + (size_t)(bl0 + rw + 16 * r) * RRANK + k4);
        As[k4 + 0][rw + 16 * r] = a.x;
        As[k4 + 1][rw + 16 * r] = a.y;
        As[k4 + 2][rw + 16 * r] = a.z;
        As[k4 + 3][rw + 16 * r] = a.w;
        float4 w = *(const float4*)(Wdt + (size_t)(d0 + rw + 16 * r) * RRANK + k4);
        Ws[k4 + 0][rw + 16 * r] = w.x;
        Ws[k4 + 1][rw + 16 * r] = w.y;
        Ws[k4 + 2][rw + 16 * r] = w.z;
        Ws[k4 + 3][rw + 16 * r] = w.w;
    }
    __syncthreads();

    const int tx = tid & 15;
    const int ty = tid >> 4;
    float acc[4][4];
#pragma unroll
    for (int i = 0; i < 4; i++)
#pragma unroll
        for (int j = 0; j < 4; j++) acc[i][j] = 0.f;

#pragma unroll 16
    for (int k = 0; k < 64; k++) {
        float4 a = *(const float4*)&As[k][ty * 4];
        float4 w = *(const float4*)&Ws[k][tx * 4];
        acc[0][0] = fmaf(a.x, w.x, acc[0][0]); acc[0][1] = fmaf(a.x, w.y, acc[0][1]);
        acc[0][2] = fmaf(a.x, w.z, acc[0][2]); acc[0][3] = fmaf(a.x, w.w, acc[0][3]);
        acc[1][0] = fmaf(a.y, w.x, acc[1][0]); acc[1][1] = fmaf(a.y, w.y, acc[1][1]);
        acc[1][2] = fmaf(a.y, w.z, acc[1][2]); acc[1][3] = fmaf(a.y, w.w, acc[1][3]);
        acc[2][0] = fmaf(a.z, w.x, acc[2][0]); acc[2][1] = fmaf(a.z, w.y, acc[2][1]);
        acc[2][2] = fmaf(a.z, w.z, acc[2][2]); acc[2][3] = fmaf(a.z, w.w, acc[2][3]);
        acc[3][0] = fmaf(a.w, w.x, acc[3][0]); acc[3][1] = fmaf(a.w, w.y, acc[3][1]);
        acc[3][2] = fmaf(a.w, w.z, acc[3][2]); acc[3][3] = fmaf(a.w, w.w, acc[3][3]);
    }
    __syncthreads();

    float2* st = (float2*)smem;       // st[d_local * 66 + t_local]
    float4 bv = *(const float4*)(bdt + d0 + tx * 4);
#pragma unroll
    for (int i = 0; i < 4; i++) {
        int bl = bl0 + ty * 4 + i;
        float4 xv = *(const float4*)(X + (size_t)bl * D_MODEL + d0 + tx * 4);
        float zs[4] = {acc[i][0] + bv.x, acc[i][1] + bv.y, acc[i][2] + bv.z, acc[i][3] + bv.w};
        float xs[4] = {xv.x, xv.y, xv.z, xv.w};
#pragma unroll
        for (int j = 0; j < 4; j++) {
            float dlt = softplusf(zs[j]);
            st[(size_t)(tx * 4 + j) * 66 + (ty * 4 + i)] = make_float2(dlt, dlt * xs[j]);
        }
    }
    __syncthreads();

    const int b  = bl0 >> 11;
    const int t0 = bl0 & (L_SEQ - 1);
    const int dl = tid >> 2;
    const int q  = tid & 3;
    const float4* srow = (const float4*)(st + (size_t)dl * 66);
    float4* dst = (float4*)(g_deltax + ((size_t)(b * D_MODEL + d0 + dl)) * L_SEQ + t0);
#pragma unroll
    for (int s = 0; s < 8; s++) dst[q * 8 + s] = srow[q * 8 + s];
}

// =====================================================================
// Chunked scan, 4-lane x 4-state layout.
// Block = 128 threads (4 warps) = 32 channels x 1 chunk.
//   g = bx & 15, c0 = (bx>>4)*32; warp w: channels c0+8w .. c0+8w+7
//   lane: q = lane&3 (states n=4q..4q+3), ch8 = lane>>2 (channel in warp)
// bc tile staged in smem (16 KB), broadcast LDS.128 reads.
// =====================================================================
__device__ __forceinline__ float ex2f(float x)
{
    float r;
    asm("ex2.approx.ftz.f32 %0, %1;" : "=f"(r) : "f"(x));
    return r;
}

// ---- pass A: per-chunk summaries P = ex2(A2*sum delta), H = local final h.
// grid 1024, block 128
__global__ __launch_bounds__(128) void k_scanA(const float* __restrict__ Alog)
{
    __shared__ float sbc[TCH][32];    // [t][2n + {B,C}]

    const int tid  = threadIdx.x;
    const int w    = tid >> 5;
    const int lane = tid & 31;
    const int q    = lane & 3;
    const int ch8  = lane >> 2;
    const int g    = blockIdx.x & (GCH - 1);
    const int c0   = (blockIdx.x >> 4) << 5;
    const int c    = c0 + w * 8 + ch8;
    const int b    = c >> 10;
    const int d    = c & (D_MODEL - 1);
    const int t0   = g * TCH;

    // stage bc tile (1024 float4, 128 threads x 8)
    {
        const float4* src = (const float4*)(g_bc + ((size_t)b * L_SEQ + t0) * 32);
        float4* dstS = (float4*)sbc;
#pragma unroll
        for (int s = 0; s < 8; s++) dstS[tid + 128 * s] = src[tid + 128 * s];
    }

    const float4 al = *(const float4*)(Alog + d * NST + 4 * q);
    const float A20 = -__expf(al.x) * 1.4426950408889634f;
    const float A21 = -__expf(al.y) * 1.4426950408889634f;
    const float A22 = -__expf(al.z) * 1.4426950408889634f;
    const float A23 = -__expf(al.w) * 1.4426950408889634f;

    const float4* __restrict__ dxp4 = (const float4*)(g_deltax + (size_t)c * L_SEQ) + (t0 >> 1);
    __syncthreads();

    float h0 = 0.f, h1 = 0.f, h2 = 0.f, h3 = 0.f, cum = 0.f;
    float4 dd = dxp4[0];
#pragma unroll 4
    for (int i = 0; i < TCH / 2; i++) {
        float4 ddn = (i < TCH / 2 - 1) ? dxp4[i + 1] : dd;
        // t = 2i
        float4 p0 = *(const float4*)&sbc[2 * i][8 * q];        // B0,C0,B1,C1
        float4 p1 = *(const float4*)&sbc[2 * i][8 * q + 4];    // B2,C2,B3,C3
        h0 = fmaf(ex2f(dd.x * A20), h0, dd.y * p0.x);
        h1 = fmaf(ex2f(dd.x * A21), h1, dd.y * p0.z);
        h2 = fmaf(ex2f(dd.x * A22), h2, dd.y * p1.x);
        h3 = fmaf(ex2f(dd.x * A23), h3, dd.y * p1.z);
        cum += dd.x;
        // t = 2i+1
        float4 p2 = *(const float4*)&sbc[2 * i + 1][8 * q];
        float4 p3 = *(const float4*)&sbc[2 * i + 1][8 * q + 4];
        h0 = fmaf(ex2f(dd.z * A20), h0, dd.w * p2.x);
        h1 = fmaf(ex2f(dd.z * A21), h1, dd.w * p2.z);
        h2 = fmaf(ex2f(dd.z * A22), h2, dd.w * p3.x);
        h3 = fmaf(ex2f(dd.z * A23), h3, dd.w * p3.z);
        cum += dd.z;
        dd = ddn;
    }

    const size_t o = ((size_t)c * GCH + g) * NST + 4 * q;
    *(float4*)(g_P + o) = make_float4(ex2f(cum * A20), ex2f(cum * A21),
                                      ex2f(cum * A22), ex2f(cum * A23));
    *(float4*)(g_H + o) = make_float4(h0, h1, h2, h3);
}

// ---- pass 2: prefix over chunks, loads hoisted for MLP. grid 128, block 256
__global__ __launch_bounds__(256) void k_fix()
{
    const int idx = blockIdx.x * 256 + threadIdx.x;   // 0..32767
    const int c = idx >> 4;
    const int n = idx & 15;
    const size_t base = (size_t)c * GCH * NST + n;

    float P[GCH], H[GCH];
#pragma unroll
    for (int g = 0; g < GCH; g++) {
        P[g] = g_P[base + (size_t)g * NST];
        H[g] = g_H[base + (size_t)g * NST];
    }
    float hs = 0.f;
#pragma unroll
    for (int g = 0; g < GCH; g++) {
        g_hs[base + (size_t)g * NST] = hs;
        hs = fmaf(P[g], hs, H[g]);
    }
}

// ---- pass B: full scan seeded with hs (hs=0 for g=0), single write of out.
// grid 1024, block 128
__global__ __launch_bounds__(128) void k_scanB(const float* __restrict__ Alog,
                                               float* __restrict__ out)
{
    __shared__ float sbc[TCH][32];

    const int tid  = threadIdx.x;
    const int w    = tid >> 5;
    const int lane = tid & 31;
    const int q    = lane & 3;
    const int ch8  = lane >> 2;
    const int g    = blockIdx.x & (GCH - 1);
    const int c0   = (blockIdx.x >> 4) << 5;
    const int c    = c0 + w * 8 + ch8;
    const int b    = c >> 10;
    const int d    = c & (D_MODEL - 1);
    const int t0   = g * TCH;

    {
        const float4* src = (const float4*)(g_bc + ((size_t)b * L_SEQ + t0) * 32);
        float4* dstS = (float4*)sbc;
#pragma unroll
        for (int s = 0; s < 8; s++) dstS[tid + 128 * s] = src[tid + 128 * s];
    }

    const float4 al = *(const float4*)(Alog + d * NST + 4 * q);
    const float A20 = -__expf(al.x) * 1.4426950408889634f;
    const float A21 = -__expf(al.y) * 1.4426950408889634f;
    const float A22 = -__expf(al.z) * 1.4426950408889634f;
    const float A23 = -__expf(al.w) * 1.4426950408889634f;

    const float4 hsv = *(const float4*)(g_hs + ((size_t)c * GCH + g) * NST + 4 * q);
    float h0 = hsv.x, h1 = hsv.y, h2 = hsv.z, h3 = hsv.w;

    const float4* __restrict__ dxp4 = (const float4*)(g_deltax + (size_t)c * L_SEQ) + (t0 >> 1);
    float* __restrict__ yo = out + ((size_t)b * L_SEQ + t0) * D_MODEL + d;
    __syncthreads();

    float4 dd = dxp4[0];
#pragma unroll 4
    for (int i = 0; i < TCH / 2; i++) {
        float4 ddn = (i < TCH / 2 - 1) ? dxp4[i + 1] : dd;
        // t = 2i
        float4 p0 = *(const float4*)&sbc[2 * i][8 * q];        // B0,C0,B1,C1
        float4 p1 = *(const float4*)&sbc[2 * i][8 * q + 4];    // B2,C2,B3,C3
        h0 = fmaf(ex2f(dd.x * A20), h0, dd.y * p0.x);
        h1 = fmaf(ex2f(dd.x * A21), h1, dd.y * p0.z);
        h2 = fmaf(ex2f(dd.x * A22), h2, dd.y * p1.x);
        h3 = fmaf(ex2f(dd.x * A23), h3, dd.y * p1.z);
        float y0 = h0 * p0.y;
        y0 = fmaf(h1, p0.w, y0);
        y0 = fmaf(h2, p1.y, y0);
        y0 = fmaf(h3, p1.w, y0);
        y0 += __shfl_xor_sync(0xffffffffu, y0, 1);
        y0 += __shfl_xor_sync(0xffffffffu, y0, 2);
        // t = 2i+1
        float4 p2 = *(const float4*)&sbc[2 * i + 1][8 * q];
        float4 p3 = *(const float4*)&sbc[2 * i + 1][8 * q + 4];
        h0 = fmaf(ex2f(dd.z * A20), h0, dd.w * p2.x);
        h1 = fmaf(ex2f(dd.z * A21), h1, dd.w * p2.z);
        h2 = fmaf(ex2f(dd.z * A22), h2, dd.w * p3.x);
        h3 = fmaf(ex2f(dd.z * A23), h3, dd.w * p3.z);
        float y1 = h0 * p2.y;
        y1 = fmaf(h1, p2.w, y1);
        y1 = fmaf(h2, p3.y, y1);
        y1 = fmaf(h3, p3.w, y1);
        y1 += __shfl_xor_sync(0xffffffffu, y1, 1);
        y1 += __shfl_xor_sync(0xffffffffu, y1, 2);

        if (q == 0) {
            yo[(size_t)(2 * i) * D_MODEL]     = y0;
            yo[(size_t)(2 * i + 1) * D_MODEL] = y1;
        }
        dd = ddn;
    }
}

// =====================================================================
extern "C" void kernel_launch(void* const* d_in, const int* in_sizes, int n_in,
                              void* d_out, int out_size)
{
    const float* X    = (const float*)d_in[0];   // hidden_states (B,L,D)
    const float* Wx   = (const float*)d_in[1];   // W_xproj (96,1024)
    const float* Wdt  = (const float*)d_in[2];   // W_dt (1024,64)
    const float* bdt  = (const float*)d_in[3];   // b_dt (1024)
    const float* Alog = (const float*)d_in[4];   // A_log (1024,16)
    float* out = (float*)d_out;

    k_zero <<<384, 256>>>();
    k_xproj<<<dim3(128, 2), 128>>>(X, Wx);
    k_delta<<<dim3(16, 64), 256>>>(Wdt, bdt, X);
    k_scanA<<<1024, 128>>>(Alog);
    k_fix  <<<128, 256>>>();
    k_scanB<<<1024, 128>>>(Alog, out);
}